// round 7
// baseline (speedup 1.0000x reference)
#include <cuda_runtime.h>
#include <cstdint>

#define Bq 256
#define Tq 64
#define Nq 128
#define Hq 512
#define Kq 640   // Nq + Hq
#define Gq 2048  // 4*Hq
#define NBLK 128
#define NTHR 512
#define SROW 36              // smem row stride (floats)
#define SB (64 * SROW)       // floats per matrix (64 rows x 32 k, padded)
#define DSMEM (8 * SB * 4)   // {Ah,Al,Wh,Wl} x 2 buffers = 73728 B

// ---------------- device scratch ----------------
__device__ __align__(16) float g_z2[Bq * Nq * Tq];  // (B,N,T)
__device__ __align__(16) float g_Wh[Gq * Kq];       // W hi (tf32), [j'][k], j'=h*4+g
__device__ __align__(16) float g_Wl[Gq * Kq];       // W lo (tf32)
__device__ __align__(16) float g_bias[Gq];
__device__ __align__(16) float g_A[2][Bq * Kq];     // double-buffered [wx(128)|h(512)]
__device__ __align__(16) float g_C[Bq * Hq];
__device__ unsigned g_bar_count;
__device__ volatile unsigned g_bar_gen;

__device__ __forceinline__ float tanh_approx(float x) {
    float y;
    asm("tanh.approx.f32 %0, %1;" : "=f"(y) : "f"(x));
    return y;
}
__device__ __forceinline__ uint32_t tf32r(float f) {
    uint32_t u;
    asm("cvt.rna.tf32.f32 %0, %1;" : "=r"(u) : "f"(f));
    return u;
}

#define MMA_TF32(c, a0, a1, a2, a3, b0, b1)                              \
    asm volatile(                                                        \
        "mma.sync.aligned.m16n8k8.row.col.f32.tf32.tf32.f32 "            \
        "{%0,%1,%2,%3},{%4,%5,%6,%7},{%8,%9},{%0,%1,%2,%3};"             \
        : "+f"((c)[0]), "+f"((c)[1]), "+f"((c)[2]), "+f"((c)[3])         \
        : "r"(a0), "r"(a1), "r"(a2), "r"(a3), "r"(b0), "r"(b1))

__device__ __forceinline__ void grid_bar() {
    __syncthreads();
    if (threadIdx.x == 0) {
        __threadfence();
        unsigned gen = g_bar_gen;
        unsigned old = atomicInc(&g_bar_count, NBLK - 1);
        if (old == NBLK - 1) {
            g_bar_gen = gen + 1;
        } else {
            while (g_bar_gen == gen) __nanosleep(64);
        }
        __threadfence();
    }
    __syncthreads();
}

// ---------------- GEMM helpers (512 threads: one float4 each) ----------------
__device__ __forceinline__ void ld_a(float4& ra, const float* Ar, int bm, int kb, int tid) {
    int row = tid >> 3, k4 = tid & 7;
    ra = *(const float4*)(Ar + (bm + row) * Kq + kb + k4 * 4);
}
__device__ __forceinline__ void ld_w(float4& rwh, float4& rwl, int jb, int kb, int tid) {
    int row = tid >> 3, k4 = tid & 7;
    rwh = *(const float4*)(g_Wh + (jb + row) * Kq + kb + k4 * 4);
    rwl = *(const float4*)(g_Wl + (jb + row) * Kq + kb + k4 * 4);
}
__device__ __forceinline__ void st_ab(float* buf, const float4 ra, const float4 rwh,
                                      const float4 rwl, int tid) {
    float* pAh = buf;
    float* pAl = buf + SB;
    float* pWh = buf + 2 * SB;
    float* pWl = buf + 3 * SB;
    int row = tid >> 3, k4 = tid & 7;
    float h0 = __uint_as_float(tf32r(ra.x));
    float h1 = __uint_as_float(tf32r(ra.y));
    float h2 = __uint_as_float(tf32r(ra.z));
    float h3 = __uint_as_float(tf32r(ra.w));
    float* a = pAh + row * SROW + k4 * 4;
    a[0] = h0; a[1] = h1; a[2] = h2; a[3] = h3;
    float* b = pAl + row * SROW + k4 * 4;
    b[0] = __uint_as_float(tf32r(ra.x - h0));
    b[1] = __uint_as_float(tf32r(ra.y - h1));
    b[2] = __uint_as_float(tf32r(ra.z - h2));
    b[3] = __uint_as_float(tf32r(ra.w - h3));
    *(float4*)(pWh + row * SROW + k4 * 4) = rwh;
    *(float4*)(pWl + row * SROW + k4 * 4) = rwl;
}
// warp tile 16x16: wm = (wid>>2)*16, wn = (wid&3)*16
__device__ __forceinline__ void mma_chunk(float (&cacc)[2][4], const float* buf,
                                          int wm, int wn, int gid, int tig) {
    const uint32_t* Ah = (const uint32_t*)(buf);
    const uint32_t* Al = (const uint32_t*)(buf + SB);
    const uint32_t* Wh = (const uint32_t*)(buf + 2 * SB);
    const uint32_t* Wl = (const uint32_t*)(buf + 3 * SB);
#pragma unroll
    for (int k8 = 0; k8 < 4; k8++) {
        int cb = k8 * 8 + tig;
        int r0 = (wm + gid) * SROW, r1 = (wm + gid + 8) * SROW;
        uint32_t ah0 = Ah[r0 + cb], ah1 = Ah[r1 + cb];
        uint32_t ah2 = Ah[r0 + cb + 4], ah3 = Ah[r1 + cb + 4];
        uint32_t al0 = Al[r0 + cb], al1 = Al[r1 + cb];
        uint32_t al2 = Al[r0 + cb + 4], al3 = Al[r1 + cb + 4];
#pragma unroll
        for (int nt = 0; nt < 2; nt++) {
            int nr = (wn + nt * 8 + gid) * SROW;
            uint32_t bh0 = Wh[nr + cb], bh1 = Wh[nr + cb + 4];
            uint32_t bl0 = Wl[nr + cb], bl1 = Wl[nr + cb + 4];
            MMA_TF32(cacc[nt], ah0, ah1, ah2, ah3, bh0, bh1);
            MMA_TF32(cacc[nt], ah0, ah1, ah2, ah3, bl0, bl1);
            MMA_TF32(cacc[nt], al0, al1, al2, al3, bh0, bh1);
        }
    }
}

// ---------------- single persistent kernel ----------------
__global__ __launch_bounds__(NTHR) void main_kernel(
    const float* __restrict__ dx, const float* __restrict__ Wa1,
    const float* __restrict__ ba1, const float* __restrict__ Wa2,
    const float* __restrict__ ba2, const float* __restrict__ Wa3,
    const float* __restrict__ ba3, const float* __restrict__ Wih,
    const float* __restrict__ Whh, const float* __restrict__ bih,
    const float* __restrict__ bhh, float* __restrict__ out) {
    extern __shared__ float dyn[];
    float* buf[2] = {dyn, dyn + 4 * SB};

    __shared__ float hs[2][1024];
    __shared__ float z1s[2][64];
    __shared__ float wa3s[64];
    __shared__ float red[2][4];

    const int cta = blockIdx.x, tid = threadIdx.x;
    const int b0 = cta * 2;
    const int cm = cta >> 5, cn = cta & 31;
    const int bm = cm * 64, jb = cn * 64;
    const int wid = tid >> 5, lane = tid & 31;
    const int wm = (wid >> 2) * 16, wn = (wid & 3) * 16;
    const int gid = lane >> 2, tig = lane & 3;

    // ================= in-kernel prep =================
    {
        const int gtid = cta * NTHR + tid, gstr = NBLK * NTHR;
        for (int idx = gtid; idx < Gq * Kq; idx += gstr) {
            int jp = idx / Kq, k = idx - jp * Kq;
            int hh = jp >> 2, gg = jp & 3, j = gg * Hq + hh;
            float v = (k < Nq) ? Wih[j * Nq + k] : Whh[j * Hq + (k - Nq)];
            float hi = __uint_as_float(tf32r(v));
            g_Wh[idx] = hi;
            g_Wl[idx] = __uint_as_float(tf32r(v - hi));
        }
        for (int idx = gtid; idx < Gq; idx += gstr) {
            int hh = idx >> 2, gg = idx & 3, j = gg * Hq + hh;
            g_bias[idx] = bih[j] + bhh[j];
        }
        for (int idx = gtid; idx < Bq * Kq; idx += gstr) {
            g_A[0][idx] = 0.f;
            g_A[1][idx] = 0.f;
        }
        for (int idx = gtid; idx < Bq * Hq; idx += gstr) g_C[idx] = 0.f;
        // z2 for this CTA's two batches (dx tile staged in dynamic smem)
        float* sdx = dyn;
        for (int bb = 0; bb < 2; bb++) {
            int b = b0 + bb;
            __syncthreads();
            for (int i = tid; i < Tq * Nq / 4; i += NTHR)
                ((float4*)sdx)[i] = ((const float4*)(dx + b * Tq * Nq))[i];
            __syncthreads();
            for (int o = tid; o < Nq * Tq; o += NTHR) {
                int s = o & 63, n = o >> 6;
                float acc = 0.f;
#pragma unroll 8
                for (int tt = 0; tt < Tq; tt++) acc += sdx[tt * Nq + n] * __ldg(&Wa2[s * Tq + tt]);
                g_z2[(b * Nq + n) * Tq + s] = acc + ba2[s];
            }
        }
        grid_bar();
    }

    if (tid < 64) wa3s[tid] = Wa3[tid];
    const float ba3v = ba3[0];
    const int pa_s = tid >> 3, pa_part = tid & 7;
    const float ba1v = ba1[pa_s];

    for (int t = 0; t < Tq; t++) {
        const int rb = t & 1;
        const float* Ar = g_A[rb];
        float* Aw = g_A[rb ^ 1];

        // ================= phase A: z1 + attention =================
        if (tid < 256) {
            int bb = tid >> 7, k4 = (tid & 127) * 4;
            *(float4*)&hs[bb][k4] = *(const float4*)(Ar + (b0 + bb) * Kq + Nq + k4);
        } else {
            int t2 = tid - 256;
            int bb = t2 >> 7, k4 = (t2 & 127) * 4;
            *(float4*)&hs[bb][512 + k4] = *(const float4*)(g_C + (b0 + bb) * Hq + k4);
        }
        __syncthreads();
        {
            const float* wr = Wa1 + pa_s * 1024 + pa_part * 128;
            const float* h0 = hs[0] + pa_part * 128;
            const float* h1 = hs[1] + pa_part * 128;
            float acc0 = 0.f, acc1 = 0.f;
#pragma unroll 8
            for (int k = 0; k < 128; k += 4) {
                float4 w = *(const float4*)(wr + k);
                acc0 += h0[k] * w.x + h0[k + 1] * w.y + h0[k + 2] * w.z + h0[k + 3] * w.w;
                acc1 += h1[k] * w.x + h1[k + 1] * w.y + h1[k + 2] * w.z + h1[k + 3] * w.w;
            }
            acc0 += __shfl_xor_sync(0xffffffffu, acc0, 1);
            acc0 += __shfl_xor_sync(0xffffffffu, acc0, 2);
            acc0 += __shfl_xor_sync(0xffffffffu, acc0, 4);
            acc1 += __shfl_xor_sync(0xffffffffu, acc1, 1);
            acc1 += __shfl_xor_sync(0xffffffffu, acc1, 2);
            acc1 += __shfl_xor_sync(0xffffffffu, acc1, 4);
            if (pa_part == 0) {
                z1s[0][pa_s] = acc0 + ba1v;
                z1s[1][pa_s] = acc1 + ba1v;
            }
        }
        __syncthreads();
        {
            // warps 8-15 duplicate warps 0-7 (same bb, n) -> idempotent writes, no divergence
            int bb = (tid >> 7) & 1, n = tid & 127;
            int b = b0 + bb;
            const float4* z2r = (const float4*)(g_z2 + (b * Nq + n) * Tq);
            float e = ba3v;
#pragma unroll
            for (int s4 = 0; s4 < Tq / 4; s4++) {
                float4 z = z2r[s4];
                int s = s4 * 4;
                e += tanh_approx(z1s[bb][s + 0] + z.x) * wa3s[s + 0];
                e += tanh_approx(z1s[bb][s + 1] + z.y) * wa3s[s + 1];
                e += tanh_approx(z1s[bb][s + 2] + z.z) * wa3s[s + 2];
                e += tanh_approx(z1s[bb][s + 3] + z.w) * wa3s[s + 3];
            }
            float m = e;
            for (int o = 16; o > 0; o >>= 1) m = fmaxf(m, __shfl_xor_sync(0xffffffffu, m, o));
            if (lane == 0) red[bb][wid & 3] = m;
            __syncthreads();
            m = fmaxf(fmaxf(red[bb][0], red[bb][1]), fmaxf(red[bb][2], red[bb][3]));
            float p = __expf(e - m);
            float sum = p;
            for (int o = 16; o > 0; o >>= 1) sum += __shfl_xor_sync(0xffffffffu, sum, o);
            __syncthreads();
            if (lane == 0) red[bb][wid & 3] = sum;
            __syncthreads();
            sum = red[bb][0] + red[bb][1] + red[bb][2] + red[bb][3];
            float w = p / sum;
            g_A[rb][b * Kq + n] = w * dx[(b * Tq + t) * Nq + n];
        }

        // ================= phase B: GEMM, h-chunks first =================
        float cacc[2][4] = {};
        float4 ra, rwh, rwl;
        ld_a(ra, Ar, bm, 128, tid);
        ld_w(rwh, rwl, jb, 128, tid);
        for (int i = 0; i < 16; i++) {
            st_ab(buf[i & 1], ra, rwh, rwl, tid);
            __syncthreads();
            if (i < 15) {
                ld_a(ra, Ar, bm, 160 + 32 * i, tid);
                ld_w(rwh, rwl, jb, 160 + 32 * i, tid);
            }
            mma_chunk(cacc, buf[i & 1], wm, wn, gid, tig);
        }
        grid_bar();  // wx from ALL CTAs now visible
        ld_a(ra, Ar, bm, 0, tid);
        ld_w(rwh, rwl, jb, 0, tid);
        for (int i = 16; i < 20; i++) {
            st_ab(buf[i & 1], ra, rwh, rwl, tid);
            __syncthreads();
            if (i < 19) {
                ld_a(ra, Ar, bm, 32 * (i - 15), tid);
                ld_w(rwh, rwl, jb, 32 * (i - 15), tid);
            }
            mma_chunk(cacc, buf[i & 1], wm, wn, gid, tig);
        }

        // fused LSTM epilogue: warp covers rows wm..wm+15, cols wn..wn+15
#pragma unroll
        for (int nt = 0; nt < 2; nt++) {
            float v0 = cacc[nt][0], v1 = cacc[nt][1];
            float v2 = cacc[nt][2], v3 = cacc[nt][3];
            float p0 = __shfl_xor_sync(0xffffffffu, v0, 1);
            float p1 = __shfl_xor_sync(0xffffffffu, v1, 1);
            float p2 = __shfl_xor_sync(0xffffffffu, v2, 1);
            float p3 = __shfl_xor_sync(0xffffffffu, v3, 1);
            if ((tig & 1) == 0) {
                int jcol = jb + wn + nt * 8 + 2 * tig;  // multiple of 4
                int h = jcol >> 2;
                float4 bias = *(const float4*)(g_bias + jcol);
                int b = bm + wm + gid;
#pragma unroll
                for (int rr = 0; rr < 2; rr++) {
                    int bb = b + rr * 8;
                    float gi = (rr ? v2 : v0) + bias.x;
                    float gf = (rr ? v3 : v1) + bias.y;
                    float gg = (rr ? p2 : p0) + bias.z;
                    float go = (rr ? p3 : p1) + bias.w;
                    float co = g_C[bb * Hq + h];
                    float si = 1.f / (1.f + __expf(-gi));
                    float sf = 1.f / (1.f + __expf(-gf));
                    float so = 1.f / (1.f + __expf(-go));
                    float cn2 = sf * co + si * tanhf(gg);
                    float hn = so * tanhf(cn2);
                    g_C[bb * Hq + h] = cn2;
                    Aw[bb * Kq + Nq + h] = hn;
                    out[(bb * Tq + t) * Hq + h] = hn;
                }
            }
        }
        grid_bar();
    }
}

extern "C" void kernel_launch(void* const* d_in, const int* in_sizes, int n_in,
                              void* d_out, int out_size) {
    const float* dx  = (const float*)d_in[0];
    const float* Wa1 = (const float*)d_in[1];
    const float* ba1 = (const float*)d_in[2];
    const float* Wa2 = (const float*)d_in[3];
    const float* ba2 = (const float*)d_in[4];
    const float* Wa3 = (const float*)d_in[5];
    const float* ba3 = (const float*)d_in[6];
    const float* Wih = (const float*)d_in[7];
    const float* Whh = (const float*)d_in[8];
    const float* bih = (const float*)d_in[9];
    const float* bhh = (const float*)d_in[10];
    float* out = (float*)d_out;

    cudaFuncSetAttribute(main_kernel, cudaFuncAttributeMaxDynamicSharedMemorySize, DSMEM);
    main_kernel<<<NBLK, NTHR, DSMEM>>>(dx, Wa1, ba1, Wa2, ba2, Wa3, ba3, Wih, Whh, bih, bhh, out);
}

// round 8
// speedup vs baseline: 1.2476x; 1.2476x over previous
#include <cuda_runtime.h>
#include <cuda_bf16.h>
#include <cstdint>

#define Bq 256
#define Tq 64
#define Nq 128
#define Hq 512
#define Kq 640   // Nq + Hq
#define Gq 2048  // 4*Hq
#define NBLK 128
#define NTHR 512
#define AS32 324                 // A smem row stride in uint32 (320 pairs + 4 pad)
#define DSMEM (2 * 64 * AS32 * 4)  // Ah + Al planes = 165888 B
#define NKK 40                   // K / 16
#define NW4 (32 * NKK * 8 * 32)  // W fragment uint4 count

// ---------------- device scratch ----------------
__device__ __align__(16) float g_z2[Bq * Nq * Tq];  // (B,N,T)
__device__ __align__(16) uint4 g_Wf[NW4];           // W in B-fragment order
__device__ __align__(16) float g_bias[Gq];
__device__ __align__(16) float g_A[2][Bq * Kq];     // double-buffered [wx(128)|h(512)]
__device__ __align__(16) float g_C[Bq * Hq];
__device__ unsigned g_bar_count;
__device__ volatile unsigned g_bar_gen;

__device__ __forceinline__ float tanh_approx(float x) {
    float y;
    asm("tanh.approx.f32 %0, %1;" : "=f"(y) : "f"(x));
    return y;
}
__device__ __forceinline__ uint32_t bpack(__nv_bfloat16 a, __nv_bfloat16 b) {
    return (uint32_t)__bfloat16_as_ushort(a) | ((uint32_t)__bfloat16_as_ushort(b) << 16);
}
__device__ __forceinline__ void split1(float v, __nv_bfloat16& hi, __nv_bfloat16& lo) {
    hi = __float2bfloat16(v);
    lo = __float2bfloat16(v - __bfloat162float(hi));
}

#define MMA_BF16(c, a0, a1, a2, a3, b0, b1)                               \
    asm volatile(                                                         \
        "mma.sync.aligned.m16n8k16.row.col.f32.bf16.bf16.f32 "            \
        "{%0,%1,%2,%3},{%4,%5,%6,%7},{%8,%9},{%0,%1,%2,%3};"              \
        : "+f"((c)[0]), "+f"((c)[1]), "+f"((c)[2]), "+f"((c)[3])          \
        : "r"(a0), "r"(a1), "r"(a2), "r"(a3), "r"(b0), "r"(b1))

__device__ __forceinline__ void grid_bar() {
    __syncthreads();
    if (threadIdx.x == 0) {
        __threadfence();
        unsigned gen = g_bar_gen;
        unsigned old = atomicInc(&g_bar_count, NBLK - 1);
        if (old == NBLK - 1) {
            g_bar_gen = gen + 1;
        } else {
            while (g_bar_gen == gen) __nanosleep(64);
        }
        __threadfence();
    }
    __syncthreads();
}

// ---------------- single persistent kernel ----------------
__global__ __launch_bounds__(NTHR) void main_kernel(
    const float* __restrict__ dx, const float* __restrict__ Wa1,
    const float* __restrict__ ba1, const float* __restrict__ Wa2,
    const float* __restrict__ ba2, const float* __restrict__ Wa3,
    const float* __restrict__ ba3, const float* __restrict__ Wih,
    const float* __restrict__ Whh, const float* __restrict__ bih,
    const float* __restrict__ bhh, float* __restrict__ out) {
    extern __shared__ float dyn[];
    uint32_t* Ash = (uint32_t*)dyn;
    uint32_t* Asl = Ash + 64 * AS32;

    __shared__ float hs[2][1024];
    __shared__ float z1s[2][64];
    __shared__ float wa3s[64];
    __shared__ float red[2][4];

    const int cta = blockIdx.x, tid = threadIdx.x;
    const int b0 = cta * 2;
    const int cm = cta >> 5, cn = cta & 31;
    const int bm = cm * 64;
    const int jb = cn * 64;
    const int wid = tid >> 5, lane = tid & 31;
    const int wm = (wid >> 2) * 16, wn = (wid & 3) * 16;
    const int gid = lane >> 2, tig = lane & 3;
    const int ng0 = (wid & 3) * 2;

    // ================= in-kernel prep =================
    {
        const int gtid = cta * NTHR + tid, gstr = NBLK * NTHR;
        // W in B-fragment order: idx = ((cn*NKK + kk)*8 + ng)*32 + lane
        for (int idx = gtid; idx < NW4; idx += gstr) {
            int ln = idx & 31;
            int v = idx >> 5;
            int ng = v & 7; v >>= 3;
            int kk = v % NKK, cw = v / NKK;
            int gg2 = ln >> 2, tg2 = ln & 3;
            int jp = cw * 64 + ng * 8 + gg2;       // permuted col j' = h*4+g
            int hh = jp >> 2, gg = jp & 3, jsrc = gg * Hq + hh;
            int k0 = kk * 16 + tg2 * 2;
            float e[4];
#pragma unroll
            for (int q = 0; q < 4; q++) {
                int k = k0 + (q >> 1) * 8 + (q & 1);
                e[q] = (k < Nq) ? Wih[jsrc * Nq + k] : Whh[jsrc * Hq + (k - Nq)];
            }
            __nv_bfloat16 h0, l0, h1, l1, h2, l2, h3, l3;
            split1(e[0], h0, l0); split1(e[1], h1, l1);
            split1(e[2], h2, l2); split1(e[3], h3, l3);
            uint4 o;
            o.x = bpack(h0, h1); o.y = bpack(h2, h3);
            o.z = bpack(l0, l1); o.w = bpack(l2, l3);
            g_Wf[idx] = o;
        }
        for (int idx = gtid; idx < Gq; idx += gstr) {
            int hh = idx >> 2, gg = idx & 3, j = gg * Hq + hh;
            g_bias[idx] = bih[j] + bhh[j];
        }
        for (int idx = gtid; idx < Bq * Kq; idx += gstr) {
            g_A[0][idx] = 0.f;
            g_A[1][idx] = 0.f;
        }
        for (int idx = gtid; idx < Bq * Hq; idx += gstr) g_C[idx] = 0.f;
        // z2 for this CTA's two batches (dx tile staged in dynamic smem)
        float* sdx = dyn;
        for (int bb = 0; bb < 2; bb++) {
            int b = b0 + bb;
            __syncthreads();
            for (int i = tid; i < Tq * Nq / 4; i += NTHR)
                ((float4*)sdx)[i] = ((const float4*)(dx + b * Tq * Nq))[i];
            __syncthreads();
            for (int o = tid; o < Nq * Tq; o += NTHR) {
                int s = o & 63, n = o >> 6;
                float acc = 0.f;
#pragma unroll 8
                for (int tt = 0; tt < Tq; tt++) acc += sdx[tt * Nq + n] * __ldg(&Wa2[s * Tq + tt]);
                g_z2[(b * Nq + n) * Tq + s] = acc + ba2[s];
            }
        }
        grid_bar();
    }

    if (tid < 64) wa3s[tid] = Wa3[tid];
    const float ba3v = ba3[0];
    const int pa_s = tid >> 3, pa_part = tid & 7;
    const float ba1v = ba1[pa_s];

    const uint4* Wcta = g_Wf + cn * (NKK * 256) + ng0 * 32 + lane;
    const int r0 = (wm + gid) * AS32, r1 = (wm + gid + 8) * AS32;

    for (int t = 0; t < Tq; t++) {
        const int rb = t & 1;
        const float* Ar = g_A[rb];
        float* Aw = g_A[rb ^ 1];

        // ================= phase A: z1 + attention =================
        if (tid < 256) {
            int bb = tid >> 7, k4 = (tid & 127) * 4;
            *(float4*)&hs[bb][k4] = *(const float4*)(Ar + (b0 + bb) * Kq + Nq + k4);
        } else {
            int t2 = tid - 256;
            int bb = t2 >> 7, k4 = (t2 & 127) * 4;
            *(float4*)&hs[bb][512 + k4] = *(const float4*)(g_C + (b0 + bb) * Hq + k4);
        }
        __syncthreads();
        {
            const float* wr = Wa1 + pa_s * 1024 + pa_part * 128;
            const float* h0 = hs[0] + pa_part * 128;
            const float* h1 = hs[1] + pa_part * 128;
            float acc0 = 0.f, acc1 = 0.f;
#pragma unroll 8
            for (int k = 0; k < 128; k += 4) {
                float4 w = *(const float4*)(wr + k);
                acc0 += h0[k] * w.x + h0[k + 1] * w.y + h0[k + 2] * w.z + h0[k + 3] * w.w;
                acc1 += h1[k] * w.x + h1[k + 1] * w.y + h1[k + 2] * w.z + h1[k + 3] * w.w;
            }
            acc0 += __shfl_xor_sync(0xffffffffu, acc0, 1);
            acc0 += __shfl_xor_sync(0xffffffffu, acc0, 2);
            acc0 += __shfl_xor_sync(0xffffffffu, acc0, 4);
            acc1 += __shfl_xor_sync(0xffffffffu, acc1, 1);
            acc1 += __shfl_xor_sync(0xffffffffu, acc1, 2);
            acc1 += __shfl_xor_sync(0xffffffffu, acc1, 4);
            if (pa_part == 0) {
                z1s[0][pa_s] = acc0 + ba1v;
                z1s[1][pa_s] = acc1 + ba1v;
            }
        }
        __syncthreads();
        {
            // warps 8-15 duplicate warps 0-7 -> idempotent writes, no divergence
            int bb = (tid >> 7) & 1, n = tid & 127;
            int b = b0 + bb;
            const float4* z2r = (const float4*)(g_z2 + (b * Nq + n) * Tq);
            float e = ba3v;
#pragma unroll
            for (int s4 = 0; s4 < Tq / 4; s4++) {
                float4 z = z2r[s4];
                int s = s4 * 4;
                e += tanh_approx(z1s[bb][s + 0] + z.x) * wa3s[s + 0];
                e += tanh_approx(z1s[bb][s + 1] + z.y) * wa3s[s + 1];
                e += tanh_approx(z1s[bb][s + 2] + z.z) * wa3s[s + 2];
                e += tanh_approx(z1s[bb][s + 3] + z.w) * wa3s[s + 3];
            }
            float m = e;
            for (int o = 16; o > 0; o >>= 1) m = fmaxf(m, __shfl_xor_sync(0xffffffffu, m, o));
            if (lane == 0) red[bb][wid & 3] = m;
            __syncthreads();
            m = fmaxf(fmaxf(red[bb][0], red[bb][1]), fmaxf(red[bb][2], red[bb][3]));
            float p = __expf(e - m);
            float sum = p;
            for (int o = 16; o > 0; o >>= 1) sum += __shfl_xor_sync(0xffffffffu, sum, o);
            __syncthreads();
            if (lane == 0) red[bb][wid & 3] = sum;
            __syncthreads();
            sum = red[bb][0] + red[bb][1] + red[bb][2] + red[bb][3];
            float w = p / sum;
            g_A[rb][b * Kq + n] = w * dx[(b * Tq + t) * Nq + n];
        }

        // ================= phase B =================
        float cacc[2][4] = {};

        // stage h-part of A (k 128..639) as bf16 hi/lo planes
#pragma unroll
        for (int i = 0; i < 16; i++) {
            int q = i * NTHR + tid;
            int row = q >> 7, c4 = q & 127;
            int k = Nq + c4 * 4;
            float4 v = *(const float4*)(Ar + (bm + row) * Kq + k);
            __nv_bfloat16 h0, l0, h1, l1, h2, l2, h3, l3;
            split1(v.x, h0, l0); split1(v.y, h1, l1);
            split1(v.z, h2, l2); split1(v.w, h3, l3);
            uint2 ph = {bpack(h0, h1), bpack(h2, h3)};
            uint2 pl = {bpack(l0, l1), bpack(l2, l3)};
            *(uint2*)(Ash + row * AS32 + (k >> 1)) = ph;
            *(uint2*)(Asl + row * AS32 + (k >> 1)) = pl;
        }
        __syncthreads();

#define KSTEP(kk, u0, u1)                                                          \
    {                                                                              \
        int kb = (kk) * 8;                                                         \
        uint32_t ah0 = Ash[r0 + kb + tig], ah1 = Ash[r1 + kb + tig];               \
        uint32_t ah2 = Ash[r0 + kb + tig + 4], ah3 = Ash[r1 + kb + tig + 4];       \
        uint32_t al0 = Asl[r0 + kb + tig], al1 = Asl[r1 + kb + tig];               \
        uint32_t al2 = Asl[r0 + kb + tig + 4], al3 = Asl[r1 + kb + tig + 4];       \
        MMA_BF16(cacc[0], ah0, ah1, ah2, ah3, u0.x, u0.y);                         \
        MMA_BF16(cacc[0], ah0, ah1, ah2, ah3, u0.z, u0.w);                         \
        MMA_BF16(cacc[0], al0, al1, al2, al3, u0.x, u0.y);                         \
        MMA_BF16(cacc[1], ah0, ah1, ah2, ah3, u1.x, u1.y);                         \
        MMA_BF16(cacc[1], ah0, ah1, ah2, ah3, u1.z, u1.w);                         \
        MMA_BF16(cacc[1], al0, al1, al2, al3, u1.x, u1.y);                         \
    }

        // h-chunks (kk 8..39) before the mid barrier
        {
            uint4 wa0 = Wcta[8 * 256], wa1 = Wcta[8 * 256 + 32];
            uint4 wb0 = Wcta[9 * 256], wb1 = Wcta[9 * 256 + 32];
            for (int kk = 8; kk < NKK; kk++) {
                uint4 u0 = wa0, u1 = wa1;
                wa0 = wb0; wa1 = wb1;
                int kn = (kk + 2 < NKK) ? kk + 2 : kk;
                wb0 = Wcta[kn * 256];
                wb1 = Wcta[kn * 256 + 32];
                KSTEP(kk, u0, u1);
            }
        }
        grid_bar();  // wx from ALL CTAs now visible

        // stage wx part (k 0..127)
#pragma unroll
        for (int i = 0; i < 4; i++) {
            int q = i * NTHR + tid;
            int row = q >> 5, c4 = q & 31;
            int k = c4 * 4;
            float4 v = *(const float4*)(Ar + (bm + row) * Kq + k);
            __nv_bfloat16 h0, l0, h1, l1, h2, l2, h3, l3;
            split1(v.x, h0, l0); split1(v.y, h1, l1);
            split1(v.z, h2, l2); split1(v.w, h3, l3);
            uint2 ph = {bpack(h0, h1), bpack(h2, h3)};
            uint2 pl = {bpack(l0, l1), bpack(l2, l3)};
            *(uint2*)(Ash + row * AS32 + (k >> 1)) = ph;
            *(uint2*)(Asl + row * AS32 + (k >> 1)) = pl;
        }
        __syncthreads();
        {
            uint4 wa0 = Wcta[0], wa1 = Wcta[32];
            uint4 wb0 = Wcta[256], wb1 = Wcta[256 + 32];
            for (int kk = 0; kk < 8; kk++) {
                uint4 u0 = wa0, u1 = wa1;
                wa0 = wb0; wa1 = wb1;
                int kn = (kk + 2 < 8) ? kk + 2 : kk;
                wb0 = Wcta[kn * 256];
                wb1 = Wcta[kn * 256 + 32];
                KSTEP(kk, u0, u1);
            }
        }

        // fused LSTM epilogue
#pragma unroll
        for (int nt = 0; nt < 2; nt++) {
            float v0 = cacc[nt][0], v1 = cacc[nt][1];
            float v2 = cacc[nt][2], v3 = cacc[nt][3];
            float p0 = __shfl_xor_sync(0xffffffffu, v0, 1);
            float p1 = __shfl_xor_sync(0xffffffffu, v1, 1);
            float p2 = __shfl_xor_sync(0xffffffffu, v2, 1);
            float p3 = __shfl_xor_sync(0xffffffffu, v3, 1);
            if ((tig & 1) == 0) {
                int jcol = jb + wn + nt * 8 + 2 * tig;  // multiple of 4
                int h = jcol >> 2;
                float4 bias = *(const float4*)(g_bias + jcol);
                int b = bm + wm + gid;
#pragma unroll
                for (int rr = 0; rr < 2; rr++) {
                    int bb = b + rr * 8;
                    float gi = (rr ? v2 : v0) + bias.x;
                    float gf = (rr ? v3 : v1) + bias.y;
                    float gg = (rr ? p2 : p0) + bias.z;
                    float go = (rr ? p3 : p1) + bias.w;
                    float co = g_C[bb * Hq + h];
                    float si = 1.f / (1.f + __expf(-gi));
                    float sf = 1.f / (1.f + __expf(-gf));
                    float so = 1.f / (1.f + __expf(-go));
                    float cn2 = sf * co + si * tanhf(gg);
                    float hn = so * tanhf(cn2);
                    g_C[bb * Hq + h] = cn2;
                    Aw[bb * Kq + Nq + h] = hn;
                    out[(bb * Tq + t) * Hq + h] = hn;
                }
            }
        }
        grid_bar();
    }
#undef KSTEP
}

extern "C" void kernel_launch(void* const* d_in, const int* in_sizes, int n_in,
                              void* d_out, int out_size) {
    const float* dx  = (const float*)d_in[0];
    const float* Wa1 = (const float*)d_in[1];
    const float* ba1 = (const float*)d_in[2];
    const float* Wa2 = (const float*)d_in[3];
    const float* ba2 = (const float*)d_in[4];
    const float* Wa3 = (const float*)d_in[5];
    const float* ba3 = (const float*)d_in[6];
    const float* Wih = (const float*)d_in[7];
    const float* Whh = (const float*)d_in[8];
    const float* bih = (const float*)d_in[9];
    const float* bhh = (const float*)d_in[10];
    float* out = (float*)d_out;

    cudaFuncSetAttribute(main_kernel, cudaFuncAttributeMaxDynamicSharedMemorySize, DSMEM);
    main_kernel<<<NBLK, NTHR, DSMEM>>>(dx, Wa1, ba1, Wa2, ba2, Wa3, ba3, Wih, Whh, bih, bhh, out);
}